// round 4
// baseline (speedup 1.0000x reference)
#include <cuda_runtime.h>

// Problem constants (fixed by the reference)
#define NN 100000
#define EE 3200000
#define FIN 128
#define HID 16
#define NCLS 40

// Scratch (device globals; no runtime allocation allowed)
__device__ float  g_dinv[NN];                 // deg, then rsqrt(deg) in-place
__device__ float  g_norm[EE];
__device__ float4 g_h[NN * 4];                // [N][16] as float4 x4
__device__ float4 g_agg1[NN * 4];
__device__ float4 g_agg2[NN * 4];

__device__ __forceinline__ void red_add_v4(float4* addr, float a, float b, float c, float d) {
    asm volatile("red.global.add.v4.f32 [%0], {%1, %2, %3, %4};"
                 :: "l"(addr), "f"(a), "f"(b), "f"(c), "f"(d)
                 : "memory");
}

// K1: deg init = 1 (self-loop)
__global__ void k_init_deg() {
    int i = blockIdx.x * blockDim.x + threadIdx.x;
    if (i < NN) g_dinv[i] = 1.0f;
}

// K2: degree accumulation (edge_index is int32: [2][EE], dst = second row)
__global__ void k_deg(const int* __restrict__ ei) {
    int e = blockIdx.x * blockDim.x + threadIdx.x;
    if (e < EE) {
        int d = ei[EE + e];
        atomicAdd(&g_dinv[d], 1.0f);
    }
}

// K3: dinv = rsqrt(deg)   (deg >= 1 always)
__global__ void k_rsqrt() {
    int i = blockIdx.x * blockDim.x + threadIdx.x;
    if (i < NN) g_dinv[i] = rsqrtf(g_dinv[i]);
}

// K4: h1 = x @ W1  (warp per node, W1 in registers, butterfly reduce)
//     also writes agg1 self-loop init = h1 * dinv^2
__global__ void k_xw1(const float* __restrict__ x, const float* __restrict__ W1) {
    const int lane  = threadIdx.x & 31;
    const int warp  = (blockIdx.x * blockDim.x + threadIdx.x) >> 5;
    const int nwarp = (gridDim.x * blockDim.x) >> 5;

    // lane owns feature rows lane, lane+32, lane+64, lane+96 of W1 [128][16]
    const float4* W1q = (const float4*)W1;
    float4 wq[16];
#pragma unroll
    for (int k = 0; k < 4; k++)
#pragma unroll
        for (int q = 0; q < 4; q++)
            wq[k * 4 + q] = W1q[(lane + 32 * k) * 4 + q];

    float* hp = (float*)g_h;
    float* ap = (float*)g_agg1;

    for (int n = warp; n < NN; n += nwarp) {
        const float* xr = x + n * FIN;
        float xv[4];
#pragma unroll
        for (int k = 0; k < 4; k++) xv[k] = xr[lane + 32 * k];

        float4 acc[4];
#pragma unroll
        for (int q = 0; q < 4; q++) {
            float4 a;
            a.x = xv[0] * wq[q].x + xv[1] * wq[4 + q].x + xv[2] * wq[8 + q].x + xv[3] * wq[12 + q].x;
            a.y = xv[0] * wq[q].y + xv[1] * wq[4 + q].y + xv[2] * wq[8 + q].y + xv[3] * wq[12 + q].y;
            a.z = xv[0] * wq[q].z + xv[1] * wq[4 + q].z + xv[2] * wq[8 + q].z + xv[3] * wq[12 + q].z;
            a.w = xv[0] * wq[q].w + xv[1] * wq[4 + q].w + xv[2] * wq[8 + q].w + xv[3] * wq[12 + q].w;
            acc[q] = a;
        }

#pragma unroll
        for (int off = 16; off > 0; off >>= 1) {
#pragma unroll
            for (int q = 0; q < 4; q++) {
                acc[q].x += __shfl_xor_sync(0xffffffffu, acc[q].x, off);
                acc[q].y += __shfl_xor_sync(0xffffffffu, acc[q].y, off);
                acc[q].z += __shfl_xor_sync(0xffffffffu, acc[q].z, off);
                acc[q].w += __shfl_xor_sync(0xffffffffu, acc[q].w, off);
            }
        }

        float dv = g_dinv[n];
        float dv2 = dv * dv;
        if (lane < 16) {
            int q = lane >> 2, c = lane & 3;
            float4 aq = acc[0];
            if (q == 1) aq = acc[1];
            if (q == 2) aq = acc[2];
            if (q == 3) aq = acc[3];
            float v = aq.x;
            if (c == 1) v = aq.y;
            if (c == 2) v = aq.z;
            if (c == 3) v = aq.w;
            hp[n * HID + lane] = v;
            ap[n * HID + lane] = v * dv2;
        }
    }
}

// K5: edge scatter, layer 1; also materializes norm[e] for layer-2 reuse
__global__ void k_scatter1(const int* __restrict__ ei) {
    int e = blockIdx.x * blockDim.x + threadIdx.x;
    if (e >= EE) return;
    int s = ei[e];
    int d = ei[EE + e];
    float w = g_dinv[s] * g_dinv[d];
    g_norm[e] = w;
    const float4* hs = &g_h[s * 4];
    float4* ad = &g_agg1[d * 4];
#pragma unroll
    for (int q = 0; q < 4; q++) {
        float4 v = hs[q];
        red_add_v4(&ad[q], v.x * w, v.y * w, v.z * w, v.w * w);
    }
}

// K6: h_act = relu(agg1 + b1); agg2 self-loop init = h_act * dinv^2
__global__ void k_relu_init(const float* __restrict__ b1) {
    int i = blockIdx.x * blockDim.x + threadIdx.x;
    if (i >= NN * HID) return;
    float v = ((const float*)g_agg1)[i] + b1[i & 15];
    v = fmaxf(v, 0.0f);
    ((float*)g_h)[i] = v;
    float dv = g_dinv[i >> 4];
    ((float*)g_agg2)[i] = v * dv * dv;
}

// K7: edge scatter, layer 2 (norm precomputed, coalesced)
__global__ void k_scatter2(const int* __restrict__ ei) {
    int e = blockIdx.x * blockDim.x + threadIdx.x;
    if (e >= EE) return;
    int s = ei[e];
    int d = ei[EE + e];
    float w = g_norm[e];
    const float4* hs = &g_h[s * 4];
    float4* ad = &g_agg2[d * 4];
#pragma unroll
    for (int q = 0; q < 4; q++) {
        float4 v = hs[q];
        red_add_v4(&ad[q], v.x * w, v.y * w, v.z * w, v.w * w);
    }
}

// K8: out = log_softmax(agg2 @ W2 + b2)
__global__ void k_final(const float* __restrict__ W2, const float* __restrict__ b2,
                        float* __restrict__ out) {
    __shared__ float4 sW2[HID * (NCLS / 4)];   // 16 x 10 float4
    __shared__ float4 sB2[NCLS / 4];
    for (int i = threadIdx.x; i < HID * (NCLS / 4); i += blockDim.x)
        sW2[i] = ((const float4*)W2)[i];
    for (int i = threadIdx.x; i < NCLS / 4; i += blockDim.x)
        sB2[i] = ((const float4*)b2)[i];
    __syncthreads();

    int n = blockIdx.x * blockDim.x + threadIdx.x;
    if (n >= NN) return;

    float a[HID];
    const float4* ar = &g_agg2[n * 4];
#pragma unroll
    for (int q = 0; q < 4; q++) {
        float4 v = ar[q];
        a[q * 4 + 0] = v.x; a[q * 4 + 1] = v.y; a[q * 4 + 2] = v.z; a[q * 4 + 3] = v.w;
    }

    float4 z[NCLS / 4];
#pragma unroll
    for (int jq = 0; jq < NCLS / 4; jq++) z[jq] = sB2[jq];

#pragma unroll
    for (int k = 0; k < HID; k++) {
        float ak = a[k];
#pragma unroll
        for (int jq = 0; jq < NCLS / 4; jq++) {
            float4 w = sW2[k * (NCLS / 4) + jq];
            z[jq].x += ak * w.x;
            z[jq].y += ak * w.y;
            z[jq].z += ak * w.z;
            z[jq].w += ak * w.w;
        }
    }

    float m = z[0].x;
#pragma unroll
    for (int jq = 0; jq < NCLS / 4; jq++) {
        m = fmaxf(m, z[jq].x); m = fmaxf(m, z[jq].y);
        m = fmaxf(m, z[jq].z); m = fmaxf(m, z[jq].w);
    }
    float s = 0.0f;
#pragma unroll
    for (int jq = 0; jq < NCLS / 4; jq++) {
        s += __expf(z[jq].x - m); s += __expf(z[jq].y - m);
        s += __expf(z[jq].z - m); s += __expf(z[jq].w - m);
    }
    float l = m + __logf(s);

    float4* o = (float4*)(out + n * NCLS);
#pragma unroll
    for (int jq = 0; jq < NCLS / 4; jq++) {
        float4 r;
        r.x = z[jq].x - l; r.y = z[jq].y - l;
        r.z = z[jq].z - l; r.w = z[jq].w - l;
        o[jq] = r;
    }
}

extern "C" void kernel_launch(void* const* d_in, const int* in_sizes, int n_in,
                              void* d_out, int out_size) {
    // Map inputs by element count (robust to ordering):
    // x: 100000*128 = 12800000, edge_index: 2*3200000 = 6400000,
    // W1: 128*16 = 2048, b1: 16, W2: 16*40 = 640, b2: 40.
    const float* x  = nullptr;
    const int*   ei = nullptr;
    const float* W1 = nullptr;
    const float* b1 = nullptr;
    const float* W2 = nullptr;
    const float* b2 = nullptr;
    for (int i = 0; i < n_in; i++) {
        switch (in_sizes[i]) {
            case NN * FIN:    x  = (const float*)d_in[i]; break;
            case 2 * EE:      ei = (const int*)d_in[i];   break;
            case FIN * HID:   W1 = (const float*)d_in[i]; break;
            case HID:         b1 = (const float*)d_in[i]; break;
            case HID * NCLS:  W2 = (const float*)d_in[i]; break;
            case NCLS:        b2 = (const float*)d_in[i]; break;
            default: break;
        }
    }
    float* out = (float*)d_out;

    k_init_deg<<<(NN + 255) / 256, 256>>>();
    k_deg<<<(EE + 511) / 512, 512>>>(ei);
    k_rsqrt<<<(NN + 255) / 256, 256>>>();
    k_xw1<<<1184, 256>>>(x, W1);
    k_scatter1<<<(EE + 511) / 512, 512>>>(ei);
    k_relu_init<<<(NN * HID + 255) / 256, 256>>>(b1);
    k_scatter2<<<(EE + 511) / 512, 512>>>(ei);
    k_final<<<(NN + 255) / 256, 256>>>(W2, b2, out);
}

// round 7
// speedup vs baseline: 1.7374x; 1.7374x over previous
#include <cuda_runtime.h>

#define NN 100000
#define EE 3200000
#define FIN 128
#define HID 16
#define NCLS 40
#define NB_SCAN 98            // ceil(NN/1024)

// Scratch (device globals)
__device__ int    g_cnt[NN];        // in-degree (without self loop)
__device__ int    g_fill[NN];
__device__ int    g_off[NN];        // exclusive prefix of cnt
__device__ int    g_blk[128];
__device__ int    g_blkpre[128];
__device__ int    g_ssrc[EE];       // src ids sorted by dst
__device__ float  g_dinv[NN];
__device__ float4 g_hs1[NN * 4];    // (x@W1) * dinv[n], [N][16]
__device__ float4 g_hs2[NN * 4];    // relu(layer1)*dinv[n]

__device__ __forceinline__ int warp_incl_scan(int v, int lane) {
#pragma unroll
    for (int off = 1; off < 32; off <<= 1) {
        int n = __shfl_up_sync(0xffffffffu, v, off);
        if (lane >= off) v += n;
    }
    return v;
}

// K1: zero counters
__global__ void k_zero() {
    int i = blockIdx.x * blockDim.x + threadIdx.x;
    if (i < NN) { g_cnt[i] = 0; g_fill[i] = 0; }
}

// K2: histogram of dst
__global__ void k_hist(const int* __restrict__ ei) {
    int e = blockIdx.x * blockDim.x + threadIdx.x;
    if (e < EE) atomicAdd(&g_cnt[ei[EE + e]], 1);
}

// K3: per-1024-block totals
__global__ void k_s1() {
    __shared__ int wsum[8];
    int t = threadIdx.x, lane = t & 31, wid = t >> 5;
    int i0 = blockIdx.x * 1024 + t * 4;
    int ts = 0;
    if (i0 + 3 < NN) {
        int4 c = *(const int4*)&g_cnt[i0];
        ts = c.x + c.y + c.z + c.w;
    } else {
        for (int k = 0; k < 4; k++) if (i0 + k < NN) ts += g_cnt[i0 + k];
    }
#pragma unroll
    for (int off = 16; off > 0; off >>= 1) ts += __shfl_xor_sync(0xffffffffu, ts, off);
    if (lane == 0) wsum[wid] = ts;
    __syncthreads();
    if (t == 0) {
        int s = 0;
#pragma unroll
        for (int w = 0; w < 8; w++) s += wsum[w];
        g_blk[blockIdx.x] = s;
    }
}

// K4: exclusive scan of block totals (single block, 128 threads)
// NOTE: second-level scan must be executed by ALL 32 lanes of warp 0
// (full-mask shfl under sub-warp divergence deadlocks on sm_100a).
__global__ void k_s2() {
    __shared__ int wpre[4];
    int t = threadIdx.x, lane = t & 31, wid = t >> 5;
    int v = (t < NB_SCAN) ? g_blk[t] : 0;
    int incl = warp_incl_scan(v, lane);
    if (lane == 31) wpre[wid] = incl;
    __syncthreads();
    if (wid == 0) {
        int wv = (lane < 4) ? wpre[lane] : 0;
        int wi = warp_incl_scan(wv, lane);   // all 32 lanes participate
        if (lane < 4) wpre[lane] = wi - wv;
    }
    __syncthreads();
    if (t < NB_SCAN) g_blkpre[t] = wpre[wid] + incl - v;
}

// K5: write per-item exclusive offsets + dinv
__global__ void k_s3() {
    __shared__ int wsum[8];
    __shared__ int wpre[8];
    int t = threadIdx.x, lane = t & 31, wid = t >> 5;
    int i0 = blockIdx.x * 1024 + t * 4;
    int v0 = 0, v1 = 0, v2 = 0, v3 = 0;
    if (i0 + 3 < NN) {
        int4 c = *(const int4*)&g_cnt[i0];
        v0 = c.x; v1 = c.y; v2 = c.z; v3 = c.w;
    } else {
        if (i0 + 0 < NN) v0 = g_cnt[i0 + 0];
        if (i0 + 1 < NN) v1 = g_cnt[i0 + 1];
        if (i0 + 2 < NN) v2 = g_cnt[i0 + 2];
        if (i0 + 3 < NN) v3 = g_cnt[i0 + 3];
    }
    int ts = v0 + v1 + v2 + v3;
    int incl = warp_incl_scan(ts, lane);
    if (lane == 31) wsum[wid] = incl;
    __syncthreads();
    if (wid == 0) {
        int wv = (lane < 8) ? wsum[lane] : 0;
        int wi = warp_incl_scan(wv, lane);   // all 32 lanes participate
        if (lane < 8) wpre[lane] = wi - wv;
    }
    __syncthreads();
    int base = g_blkpre[blockIdx.x] + wpre[wid] + incl - ts;
    if (i0 + 0 < NN) { g_off[i0 + 0] = base;                g_dinv[i0 + 0] = rsqrtf((float)(v0 + 1)); }
    if (i0 + 1 < NN) { g_off[i0 + 1] = base + v0;           g_dinv[i0 + 1] = rsqrtf((float)(v1 + 1)); }
    if (i0 + 2 < NN) { g_off[i0 + 2] = base + v0 + v1;      g_dinv[i0 + 2] = rsqrtf((float)(v2 + 1)); }
    if (i0 + 3 < NN) { g_off[i0 + 3] = base + v0 + v1 + v2; g_dinv[i0 + 3] = rsqrtf((float)(v3 + 1)); }
}

// K6: place edges sorted by destination
__global__ void k_place(const int* __restrict__ ei) {
    int e = blockIdx.x * blockDim.x + threadIdx.x;
    if (e >= EE) return;
    int s = ei[e];
    int d = ei[EE + e];
    int p = g_off[d] + atomicAdd(&g_fill[d], 1);
    g_ssrc[p] = s;
}

// K7: hs1 = (x @ W1) * dinv   — smem-tiled, 64 nodes/block, no shuffles
__global__ __launch_bounds__(256) void k_xw1(const float* __restrict__ x,
                                             const float* __restrict__ W1) {
    __shared__ float4 sx[64 * 33];     // padded row stride 33 float4
    __shared__ float4 sW[512];         // W1 [128][16] as float4
    int t = threadIdx.x;
    int n0 = blockIdx.x * 64;

    for (int i = t; i < 512; i += 256) sW[i] = ((const float4*)W1)[i];
#pragma unroll
    for (int r = 0; r < 8; r++) {
        int idx = t + 256 * r;          // 0..2047
        int row = idx >> 5, col = idx & 31;
        int n = n0 + row;
        float4 v = make_float4(0.f, 0.f, 0.f, 0.f);
        if (n < NN) v = ((const float4*)x)[n * 32 + col];
        sx[row * 33 + col] = v;
    }
    __syncthreads();

    int node = t >> 2, q = t & 3;
    int n = n0 + node;
    float4 acc = make_float4(0.f, 0.f, 0.f, 0.f);
#pragma unroll
    for (int k4 = 0; k4 < 32; k4++) {
        float4 xv = sx[node * 33 + k4];
#pragma unroll
        for (int c = 0; c < 4; c++) {
            float a = (c == 0) ? xv.x : (c == 1) ? xv.y : (c == 2) ? xv.z : xv.w;
            float4 w = sW[(k4 * 4 + c) * 4 + q];
            acc.x += a * w.x; acc.y += a * w.y; acc.z += a * w.z; acc.w += a * w.w;
        }
    }
    if (n < NN) {
        float dv = g_dinv[n];
        g_hs1[n * 4 + q] = make_float4(acc.x * dv, acc.y * dv, acc.z * dv, acc.w * dv);
    }
}

// K8: layer-1 gather + bias + relu; writes hs2 = relu(agg1)*dinv
__global__ __launch_bounds__(256) void k_gather1(const float* __restrict__ b1) {
    int warp = (blockIdx.x * blockDim.x + threadIdx.x) >> 5;
    if (warp >= NN) return;
    int lane = threadIdx.x & 31;
    int q = lane & 3, g = lane >> 2;
    int d = warp;
    int base = g_off[d], deg = g_cnt[d];
    float4 acc = make_float4(0.f, 0.f, 0.f, 0.f);
    for (int j = g; j < deg; j += 8) {
        int s = g_ssrc[base + j];
        float4 v = g_hs1[s * 4 + q];
        acc.x += v.x; acc.y += v.y; acc.z += v.z; acc.w += v.w;
    }
#pragma unroll
    for (int off = 16; off >= 4; off >>= 1) {
        acc.x += __shfl_xor_sync(0xffffffffu, acc.x, off);
        acc.y += __shfl_xor_sync(0xffffffffu, acc.y, off);
        acc.z += __shfl_xor_sync(0xffffffffu, acc.z, off);
        acc.w += __shfl_xor_sync(0xffffffffu, acc.w, off);
    }
    float4 self = g_hs1[d * 4 + q];
    float dv = g_dinv[d];
    float4 bq = ((const float4*)b1)[q];
    float4 h;
    h.x = fmaxf(dv * (acc.x + self.x) + bq.x, 0.f) * dv;
    h.y = fmaxf(dv * (acc.y + self.y) + bq.y, 0.f) * dv;
    h.z = fmaxf(dv * (acc.z + self.z) + bq.z, 0.f) * dv;
    h.w = fmaxf(dv * (acc.w + self.w) + bq.w, 0.f) * dv;
    if (lane < 4) g_hs2[d * 4 + q] = h;
}

// K9: layer-2 gather + W2 GEMM + log_softmax, fused
__global__ __launch_bounds__(256) void k_gather2(const float* __restrict__ W2,
                                                 const float* __restrict__ b2,
                                                 float* __restrict__ out) {
    __shared__ float sW2[HID * NCLS];
    __shared__ float sB2[NCLS];
    for (int i = threadIdx.x; i < HID * NCLS; i += blockDim.x) sW2[i] = W2[i];
    for (int i = threadIdx.x; i < NCLS; i += blockDim.x) sB2[i] = b2[i];
    __syncthreads();

    int warp = (blockIdx.x * blockDim.x + threadIdx.x) >> 5;
    if (warp >= NN) return;
    int lane = threadIdx.x & 31;
    int q = lane & 3, g = lane >> 2;
    int d = warp;
    int base = g_off[d], deg = g_cnt[d];
    float4 acc = make_float4(0.f, 0.f, 0.f, 0.f);
    for (int j = g; j < deg; j += 8) {
        int s = g_ssrc[base + j];
        float4 v = g_hs2[s * 4 + q];
        acc.x += v.x; acc.y += v.y; acc.z += v.z; acc.w += v.w;
    }
#pragma unroll
    for (int off = 16; off >= 4; off >>= 1) {
        acc.x += __shfl_xor_sync(0xffffffffu, acc.x, off);
        acc.y += __shfl_xor_sync(0xffffffffu, acc.y, off);
        acc.z += __shfl_xor_sync(0xffffffffu, acc.z, off);
        acc.w += __shfl_xor_sync(0xffffffffu, acc.w, off);
    }
    float4 self = g_hs2[d * 4 + q];
    float dv = g_dinv[d];
    float4 agg;
    agg.x = dv * (acc.x + self.x);
    agg.y = dv * (acc.y + self.y);
    agg.z = dv * (acc.z + self.z);
    agg.w = dv * (acc.w + self.w);

    // broadcast all 16 agg values to every lane
    float a[HID];
#pragma unroll
    for (int k = 0; k < HID; k++) {
        int comp = k & 3;
        float send = (comp == 0) ? agg.x : (comp == 1) ? agg.y : (comp == 2) ? agg.z : agg.w;
        a[k] = __shfl_sync(0xffffffffu, send, k >> 2);
    }

    int j = lane;                 // class j and (j<8) class 32+j
    int j2 = 32 + (j & 7);
    float z1 = sB2[j];
    float z2 = sB2[j2];
#pragma unroll
    for (int k = 0; k < HID; k++) {
        z1 += a[k] * sW2[k * NCLS + j];
        z2 += a[k] * sW2[k * NCLS + j2];
    }
    bool has2 = (j < 8);

    float lm = has2 ? fmaxf(z1, z2) : z1;
#pragma unroll
    for (int off = 16; off > 0; off >>= 1)
        lm = fmaxf(lm, __shfl_xor_sync(0xffffffffu, lm, off));
    float ls = __expf(z1 - lm) + (has2 ? __expf(z2 - lm) : 0.f);
#pragma unroll
    for (int off = 16; off > 0; off >>= 1)
        ls += __shfl_xor_sync(0xffffffffu, ls, off);
    float l = lm + __logf(ls);

    out[d * NCLS + j] = z1 - l;
    if (has2) out[d * NCLS + j2] = z2 - l;
}

extern "C" void kernel_launch(void* const* d_in, const int* in_sizes, int n_in,
                              void* d_out, int out_size) {
    const float* x  = nullptr;
    const int*   ei = nullptr;
    const float* W1 = nullptr;
    const float* b1 = nullptr;
    const float* W2 = nullptr;
    const float* b2 = nullptr;
    for (int i = 0; i < n_in; i++) {
        switch (in_sizes[i]) {
            case NN * FIN:    x  = (const float*)d_in[i]; break;
            case 2 * EE:      ei = (const int*)d_in[i];   break;
            case FIN * HID:   W1 = (const float*)d_in[i]; break;
            case HID:         b1 = (const float*)d_in[i]; break;
            case HID * NCLS:  W2 = (const float*)d_in[i]; break;
            case NCLS:        b2 = (const float*)d_in[i]; break;
            default: break;
        }
    }
    float* out = (float*)d_out;

    k_zero<<<(NN + 255) / 256, 256>>>();
    k_hist<<<(EE + 511) / 512, 512>>>(ei);
    k_s1<<<NB_SCAN, 256>>>();
    k_s2<<<1, 128>>>();
    k_s3<<<NB_SCAN, 256>>>();
    k_place<<<(EE + 511) / 512, 512>>>(ei);
    k_xw1<<<(NN + 63) / 64, 256>>>(x, W1);
    k_gather1<<<(NN * 32 + 255) / 256, 256>>>(b1);
    k_gather2<<<(NN * 32 + 255) / 256, 256>>>(W2, b2, out);
}